// round 17
// baseline (speedup 1.0000x reference)
#include <cuda_runtime.h>
#include <cuda_bf16.h>
#include <cstdint>

#define BB 8
#define SS 4096           // WIDTH*WIDTH
#define EE 128
#define WIDTH 64
#define NEDGE 512         // 32 paths * 16 edges per batch
#define MAXL 32           // cap on same-src edge list
#define UU 4              // edges per fused block
#define FILL_BLOCKS 2048  // 16 MB attn fill: 2048 blocks x 512 thr x 16 B

// Combined weights: Wc = Wv @ Wp, bc = bv @ Wp
__device__ float g_Wc[EE * EE];
__device__ float g_bc[EE];

// ---------------------------------------------------------------------------
// prep_fill: blocks [0,128)   -> Wc row i via split-K (4 chunks x 32 k-steps)
//            blocks [128, +FILL_BLOCKS) -> bp broadcast fill of attn region
__global__ __launch_bounds__(512)
void prep_fill_kernel(const float* __restrict__ Wv,
                      const float* __restrict__ Wp,
                      const float* __restrict__ bv,
                      float4* __restrict__ attn4,
                      const float4* __restrict__ bp4) {
    int t = threadIdx.x;
    if (blockIdx.x < EE) {
        int i  = blockIdx.x;
        int j  = t & 127;
        int kc = t >> 7;                  // 0..3
        __shared__ float part[4][EE];
        __shared__ float wvrow[EE];
        if (kc == 0) wvrow[j] = Wv[i * EE + j];
        __syncthreads();

        float acc = 0.0f;
        int k0 = kc * 32;
        #pragma unroll
        for (int k = 0; k < 32; k++)
            acc = fmaf(wvrow[k0 + k], Wp[(k0 + k) * EE + j], acc);
        part[kc][j] = acc;
        __syncthreads();
        if (kc == 0) {
            g_Wc[i * EE + j] = (part[0][j] + part[1][j]) + (part[2][j] + part[3][j]);
        } else if (i == 0 && kc == 1) {
            float b = 0.0f;
            #pragma unroll 16
            for (int k = 0; k < EE; k++)
                b = fmaf(bv[k], Wp[k * EE + j], b);
            g_bc[j] = b;
        }
    } else {
        unsigned idx = (blockIdx.x - EE) * 512u + t;
        attn4[idx] = bp4[t & 31];
    }
}

// ---------------------------------------------------------------------------
// Fused output + adjacency ones: 4 edges per block, 256 threads (1024 x 256).
// Thread (e = tid&127, h = tid>>7). Halves split the k-dimension of the
// matvec so each Wc element is read ONCE per block (4-row amortization)
// while warp concurrency matches the proven 2048x128 shape.
__global__ __launch_bounds__(256)
void fused_out_kernel(float* __restrict__ attn,
                      float* __restrict__ A1,
                      float* __restrict__ A2,
                      const float* __restrict__ values,
                      const float* __restrict__ bp,
                      const int* __restrict__ edges) {
    __shared__ int ssrc[NEDGE];
    __shared__ int sdst[NEDGE];
    __shared__ int list[UU][MAXL];
    __shared__ int nlist[UU];
    __shared__ int dupflag[UU];
    __shared__ int sm_m[UU];
    __shared__ float accv[UU][EE];
    __shared__ float po[UU][EE];       // half-1 matvec partials

    int b = blockIdx.y;
    int i0 = blockIdx.x * UU;
    int tid = threadIdx.x;
    int e = tid & 127;
    int h = tid >> 7;                  // 0 or 1

    // load 512 edges: 2 per thread
    const int4* eg = (const int4*)(edges + (size_t)b * NEDGE * 4);
    #pragma unroll
    for (int q = 0; q < 2; q++) {
        int t = tid + q * 256;
        int4 v = eg[t];
        ssrc[t] = v.y * WIDTH + v.x;
        sdst[t] = v.w * WIDTH + v.z;
    }
    if (tid < UU) { nlist[tid] = 0; dupflag[tid] = 0; }
    __syncthreads();

    // adjacency ones (after memset in stream order; idempotent)
    if (tid < UU) {
        int i = i0 + tid;
        size_t off = ((size_t)b * SS + ssrc[i]) * SS + sdst[i];
        A1[off] = 1.0f;
        A2[off] = 1.0f;
    }

    int my[UU];
    #pragma unroll
    for (int r = 0; r < UU; r++) my[r] = ssrc[i0 + r];

    // first-src check + same-src dst collection (2 smem slots per thread)
    #pragma unroll
    for (int q = 0; q < 2; q++) {
        int t = tid + q * 256;
        int s = ssrc[t];
        #pragma unroll
        for (int r = 0; r < UU; r++) {
            if (s == my[r]) {
                if (t < i0 + r) dupflag[r] = 1;
                int p = atomicAdd(&nlist[r], 1);
                if (p < MAXL) list[r][p] = sdst[t];
            }
        }
    }
    __syncthreads();

    int d[UU];
    int alldup = 1;
    #pragma unroll
    for (int r = 0; r < UU; r++) { d[r] = dupflag[r]; alldup &= d[r]; }
    if (alldup) return;

    // unique-by-value sums: half h handles rows 2h, 2h+1
    #pragma unroll
    for (int q = 0; q < 2; q++) {
        int r = 2 * h + q;
        float acc = 0.0f;
        int mr = 0;
        if (!d[r]) {
            int n = nlist[r] < MAXL ? nlist[r] : MAXL;
            for (int qq = 0; qq < n; qq++) {
                int dd = list[r][qq];
                bool uniq = true;
                for (int p = 0; p < qq; p++)
                    if (list[r][p] == dd) { uniq = false; break; }
                if (uniq) {
                    acc += values[((size_t)b * SS + dd) * EE + e];
                    mr++;
                }
            }
        }
        accv[r][e] = acc;
        if (e == 0) sm_m[r] = mr;
    }
    __syncthreads();

    // split-k matvec: half h covers k in [64h, 64h+64), Wc read once per block
    float o[UU];
    #pragma unroll
    for (int r = 0; r < UU; r++) o[r] = 0.0f;
    int k0 = h * 64;
    #pragma unroll 8
    for (int k = 0; k < 64; k++) {
        float w = g_Wc[(k0 + k) * EE + e];
        #pragma unroll
        for (int r = 0; r < UU; r++)
            o[r] = fmaf(accv[r][k0 + k], w, o[r]);
    }
    if (h == 1) {
        #pragma unroll
        for (int r = 0; r < UU; r++) po[r][e] = o[r];
    }
    __syncthreads();

    // half 0 reduces + writes outputs
    if (h == 0) {
        float bce = g_bc[e], bpe = bp[e];
        #pragma unroll
        for (int r = 0; r < UU; r++) {
            if (!d[r]) {
                float res = o[r] + po[r][e] + fmaf((float)sm_m[r], bce, bpe);
                attn[((size_t)b * SS + my[r]) * EE + e] = res;
            }
        }
    }
}

// ---------------------------------------------------------------------------
extern "C" void kernel_launch(void* const* d_in, const int* in_sizes, int n_in,
                              void* d_out, int out_size) {
    (void)in_sizes; (void)n_in; (void)out_size;

    const float* values = (const float*)d_in[2];
    const int*   edges  = (const int*)  d_in[3];
    const float* Wv     = (const float*)d_in[8];
    const float* bv     = (const float*)d_in[9];
    const float* Wp     = (const float*)d_in[10];
    const float* bp     = (const float*)d_in[11];

    float* out  = (float*)d_out;
    float* attn = out;                                    // [B,S,E]
    float* A1   = out + (size_t)BB * SS * EE;             // [B,S,S]
    float* A2   = A1 + (size_t)BB * SS * SS;              // [B,S,S]

    // 1) bulk zeros via memset (fastest store path, ~147 us)
    cudaMemsetAsync(A1, 0, 2ull * BB * SS * SS * sizeof(float));

    // 2) combined weights + bp broadcast fill, one launch (~4 us)
    prep_fill_kernel<<<EE + FILL_BLOCKS, 512>>>(Wv, Wp, bv,
                                                (float4*)attn, (const float4*)bp);

    // 3) fused sparse output + adjacency ones (1024 x 256)
    {
        dim3 grid(NEDGE / UU, BB);
        fused_out_kernel<<<grid, 256>>>(attn, A1, A2, values, bp, edges);
    }
}